// round 15
// baseline (speedup 1.0000x reference)
#include <cuda_runtime.h>

// Problem constants (fixed by setup_inputs)
#define Bq      128
#define Nq      8192
#define THREADS 1024
#define WARPS   32
#define PPW     256        // points per warp
#define NINTV   32         // 8 points per interval

#define LOG2E 1.4426950408889634f

typedef unsigned long long ull;

// ---- Blackwell packed fp32x2 helpers (FFMA2 only reachable via PTX) ----
static __device__ __forceinline__ ull pk2(float lo, float hi) {
    ull r; asm("mov.b64 %0, {%1, %2};" : "=l"(r) : "f"(lo), "f"(hi)); return r;
}
static __device__ __forceinline__ ull ffma2(ull a, ull b, ull c) {
    ull d; asm("fma.rn.f32x2 %0, %1, %2, %3;" : "=l"(d) : "l"(a), "l"(b), "l"(c)); return d;
}
static __device__ __forceinline__ float2 upk2(ull v) {
    float2 f; asm("mov.b64 {%0, %1}, %2;" : "=f"(f.x), "=f"(f.y) : "l"(v)); return f;
}
static __device__ __forceinline__ ull relu2(ull v) {
    float2 f = upk2(v);
    return pk2(fmaxf(f.x, 0.f), fmaxf(f.y, 0.f));
}

__global__ __launch_bounds__(THREADS, 1)
void mha_fused_kernel(const float* __restrict__ radar_xy,
                      const float* __restrict__ radar_dir,
                      const float* __restrict__ pts,
                      const float* __restrict__ enc_w1,
                      const float* __restrict__ enc_b1,
                      const float* __restrict__ enc_w2,
                      const float* __restrict__ enc_b2,
                      const float* __restrict__ sc_w1,
                      const float* __restrict__ sc_b1,
                      const float* __restrict__ sc_w2,
                      const float* __restrict__ sc_b2,
                      const float* __restrict__ out_w1,
                      const float* __restrict__ out_b1,
                      const float* __restrict__ out_w2,
                      const float* __restrict__ out_b2,
                      float* __restrict__ out)
{
    __shared__ ulonglong2 sAB[4][32];    // (a-pair px, b-pair py) — read once to regs
    __shared__ ulonglong2 sCV[4][32];    // (c-pair bias, v-pair w2) — 4 LDS.128 per stage-A
    __shared__ ull        sE1p[32], sE2p[32], sBEp[32];  // encoder packed (j, j+32)
    // Weight slots, single buffer: per warp 16 float4 = [half(2)][pt(4)][head-pair(2)]
    __shared__ float4     sWexp[WARPS][16];
    __shared__ __align__(16) float sRed[WARPS][4][64];   // pooled partials (written after loop)
    __shared__ float      sWsum[WARPS][4];
    __shared__ float      sSum[4];

    // Point stash lives in sRed's dead space during the loop: [2][WARPS][4] float4 = 4 KB
    float4* sPtsBase = reinterpret_cast<float4*>(&sRed[0][0][0]);
    // Finalize arrays overlay sWexp (dead after the loop): 256 + 256 + 64 floats
    float* sPooledF = reinterpret_cast<float*>(&sWexp[0][0]);
    float* sCtxF    = sPooledF + 256;
    float* sOF      = sCtxF + 256;

    const int b    = blockIdx.x;
    const int tid  = threadIdx.x;
    const int warp = tid >> 5;
    const int lane = tid & 31;

    const float r0 = radar_xy[b*2+0], r1 = radar_xy[b*2+1];
    const float r2 = radar_dir[b*2+0], r3 = radar_dir[b*2+1];

    // ---------------- Staging (identical to R9/R13) ----------------
    if (tid < 128) {
        const int k = tid >> 5, hs = tid & 31;
        const int hh = hs >> 3, j = (hs & 7) * 8 + k * 2;
        const float* w = sc_w1 + (size_t)hh * 384;
        const float c0 = sc_b1[hh*64+j]   + r0*w[j]   + r1*w[64+j]   + r2*w[128+j]   + r3*w[192+j];
        const float c1 = sc_b1[hh*64+j+1] + r0*w[j+1] + r1*w[64+j+1] + r2*w[128+j+1] + r3*w[192+j+1];
        ulonglong2 cv;
        cv.x = pk2(c0, c1);
        cv.y = pk2(sc_w2[hh*64+j], sc_w2[hh*64+j+1]);
        sCV[k][hs] = cv;
    } else if (tid < 224) {
        const int idx = tid - 128, arr = idx >> 5, l = idx & 31;
        if (arr == 0)      sE1p[l] = pk2(enc_w1[256+l], enc_w1[256+l+32]);
        else if (arr == 1) sE2p[l] = pk2(enc_w1[320+l], enc_w1[320+l+32]);
        else {
            const float b0 = enc_b1[l]    + r0*enc_w1[l]     + r1*enc_w1[64+l]
                                          + r2*enc_w1[128+l]  + r3*enc_w1[192+l];
            const float b1 = enc_b1[l+32] + r0*enc_w1[l+32]  + r1*enc_w1[64+l+32]
                                          + r2*enc_w1[128+l+32] + r3*enc_w1[192+l+32];
            sBEp[l] = pk2(b0, b1);
        }
    } else if (tid >= 256 && tid < 384) {
        const int idx = tid - 256;
        const int k = idx >> 5, hs = idx & 31;
        const int hh = hs >> 3, j = (hs & 7) * 8 + k * 2;
        const float* w = sc_w1 + (size_t)hh * 384;
        ulonglong2 ab;
        ab.x = pk2(w[256+j], w[256+j+1]);   // row 4: px coeffs
        ab.y = pk2(w[320+j], w[320+j+1]);   // row 5: py coeffs
        sAB[k][hs] = ab;
    }
    __syncthreads();

    // ---------------- Per-lane constants (R9 register budget) ----------------
    const int h = lane >> 3, s = lane & 7;
    const float b2l = sc_b2[h] * LOG2E;
    // After the butterfly, lane s holds point p(s) = (s&1)*2 + ((s>>1)&1)
    const int pOwn = ((s & 1) << 1) + ((s >> 1) & 1);
    const bool sel1 = (s & 1) != 0, sel2 = (s & 2) != 0;

    ull aK[4], bK[4];
    #pragma unroll
    for (int k = 0; k < 4; k++) {
        ulonglong2 t = sAB[k][lane]; aK[k] = t.x; bK[k] = t.y;
    }
    const ull e1p = sE1p[lane], e2p = sE2p[lane], bep = sBEp[lane];

    ull P0 = 0ull, P1 = 0ull, P2 = 0ull, P3 = 0ull;   // pooled (feat lane, lane+32) x 4 heads
    float sOwn = 0.f;

    const float4* P4 = reinterpret_cast<const float4*>(pts)
                     + ((size_t)b * (Nq/2) + (size_t)warp * (PPW/2));

    float2* wp = reinterpret_cast<float2*>(
        reinterpret_cast<float*>(&sWexp[warp][0]) + pOwn * 8 + h * 2);
    const ulonglong2* WV = reinterpret_cast<const ulonglong2*>(&sWexp[warp][0]);

    // ---- Stage A: logits (4 pts), butterfly, exp, STS (R9 form) ----
    auto stageA = [&](const float4 qa, const float4 qb, float2* slot) {
        const ull px0 = pk2(qa.x,qa.x), py0 = pk2(qa.y,qa.y);
        const ull px1 = pk2(qa.z,qa.z), py1 = pk2(qa.w,qa.w);
        const ull px2 = pk2(qb.x,qb.x), py2 = pk2(qb.y,qb.y);
        const ull px3 = pk2(qb.z,qb.z), py3 = pk2(qb.w,qb.w);

        ull ac0, ac1, ac2, ac3;
        {
            ulonglong2 cv = sCV[0][lane];
            ac0 = ffma2(relu2(ffma2(py0,bK[0], ffma2(px0,aK[0], cv.x))), cv.y, 0ull);
            ac1 = ffma2(relu2(ffma2(py1,bK[0], ffma2(px1,aK[0], cv.x))), cv.y, 0ull);
            ac2 = ffma2(relu2(ffma2(py2,bK[0], ffma2(px2,aK[0], cv.x))), cv.y, 0ull);
            ac3 = ffma2(relu2(ffma2(py3,bK[0], ffma2(px3,aK[0], cv.x))), cv.y, 0ull);
            cv = sCV[1][lane];
            ac0 = ffma2(relu2(ffma2(py0,bK[1], ffma2(px0,aK[1], cv.x))), cv.y, ac0);
            ac1 = ffma2(relu2(ffma2(py1,bK[1], ffma2(px1,aK[1], cv.x))), cv.y, ac1);
            ac2 = ffma2(relu2(ffma2(py2,bK[1], ffma2(px2,aK[1], cv.x))), cv.y, ac2);
            ac3 = ffma2(relu2(ffma2(py3,bK[1], ffma2(px3,aK[1], cv.x))), cv.y, ac3);
            cv = sCV[2][lane];
            ac0 = ffma2(relu2(ffma2(py0,bK[2], ffma2(px0,aK[2], cv.x))), cv.y, ac0);
            ac1 = ffma2(relu2(ffma2(py1,bK[2], ffma2(px1,aK[2], cv.x))), cv.y, ac1);
            ac2 = ffma2(relu2(ffma2(py2,bK[2], ffma2(px2,aK[2], cv.x))), cv.y, ac2);
            ac3 = ffma2(relu2(ffma2(py3,bK[2], ffma2(px3,aK[2], cv.x))), cv.y, ac3);
            cv = sCV[3][lane];
            ac0 = ffma2(relu2(ffma2(py0,bK[3], ffma2(px0,aK[3], cv.x))), cv.y, ac0);
            ac1 = ffma2(relu2(ffma2(py1,bK[3], ffma2(px1,aK[3], cv.x))), cv.y, ac1);
            ac2 = ffma2(relu2(ffma2(py2,bK[3], ffma2(px2,aK[3], cv.x))), cv.y, ac2);
            ac3 = ffma2(relu2(ffma2(py3,bK[3], ffma2(px3,aK[3], cv.x))), cv.y, ac3);
        }
        float2 t;
        t = upk2(ac0); float a0 = t.x + t.y;
        t = upk2(ac1); float a1 = t.x + t.y;
        t = upk2(ac2); float a2 = t.x + t.y;
        t = upk2(ac3); float a3 = t.x + t.y;

        // batched butterfly over 8 lanes: 4 shfl / 4 points
        const float r0s = __shfl_xor_sync(0xffffffffu, sel1 ? a0 : a2, 1);
        const float r1s = __shfl_xor_sync(0xffffffffu, sel1 ? a1 : a3, 1);
        a0 = (sel1 ? a2 : a0) + r0s;
        a1 = (sel1 ? a3 : a1) + r1s;
        const float r2s = __shfl_xor_sync(0xffffffffu, sel2 ? a0 : a1, 2);
        float v = (sel2 ? a1 : a0) + r2s;
        v += __shfl_xor_sync(0xffffffffu, v, 4);

        const float w = exp2f(fmaf(v, LOG2E, b2l));
        sOwn += w;                          // each (pt,h) counted twice per 8-group (x0.5 later)
        if (s < 4) slot[0] = make_float2(w, w);
    };

    // ---- Stage B: encoder + paired pooling (4 pts), packed (R13 form) ----
    auto stageB = [&](const float4 qa, const float4 qb, const ulonglong2* wv) {
        ull h2; ulonglong2 w01, w23;

        h2 = relu2(ffma2(pk2(qa.y,qa.y), e2p, ffma2(pk2(qa.x,qa.x), e1p, bep)));
        w01 = wv[0]; w23 = wv[1];
        P0 = ffma2(w01.x, h2, P0); P1 = ffma2(w01.y, h2, P1);
        P2 = ffma2(w23.x, h2, P2); P3 = ffma2(w23.y, h2, P3);

        h2 = relu2(ffma2(pk2(qa.w,qa.w), e2p, ffma2(pk2(qa.z,qa.z), e1p, bep)));
        w01 = wv[2]; w23 = wv[3];
        P0 = ffma2(w01.x, h2, P0); P1 = ffma2(w01.y, h2, P1);
        P2 = ffma2(w23.x, h2, P2); P3 = ffma2(w23.y, h2, P3);

        h2 = relu2(ffma2(pk2(qb.y,qb.y), e2p, ffma2(pk2(qb.x,qb.x), e1p, bep)));
        w01 = wv[4]; w23 = wv[5];
        P0 = ffma2(w01.x, h2, P0); P1 = ffma2(w01.y, h2, P1);
        P2 = ffma2(w23.x, h2, P2); P3 = ffma2(w23.y, h2, P3);

        h2 = relu2(ffma2(pk2(qb.w,qb.w), e2p, ffma2(pk2(qb.z,qb.z), e1p, bep)));
        w01 = wv[6]; w23 = wv[7];
        P0 = ffma2(w01.x, h2, P0); P1 = ffma2(w01.y, h2, P1);
        P2 = ffma2(w23.x, h2, P2); P3 = ffma2(w23.y, h2, P3);
    };

    // ---------------- Main loop: 8 points per interval, 2 syncs ----------------
    #pragma unroll 1
    for (int t = 0; t < NINTV; t++) {
        float4* stash = sPtsBase + (((t & 1) * WARPS + warp) << 2);

        const float4 qa = __ldg(P4 + 4*t);
        const float4 qb = __ldg(P4 + 4*t + 1);
        const float4 qc = __ldg(P4 + 4*t + 2);
        const float4 qd = __ldg(P4 + 4*t + 3);
        // Points are warp-uniform: lanes 0-3 stash them (1-2 crossbar phases total)
        if (lane == 0) stash[0] = qa;
        if (lane == 1) stash[1] = qb;
        if (lane == 2) stash[2] = qc;
        if (lane == 3) stash[3] = qd;
        __syncwarp();                       // sync1: stash visible

        stageA(qa, qb, wp);                 // chain 1
        stageA(stash[2], stash[3], wp + 16);// chain 2 (independent — interleaves with chain 1)

        __syncwarp();                       // sync2: weights visible

        stageB(stash[0], stash[1], WV);     // broadcast LDS reloads, packed pooling
        stageB(stash[2], stash[3], WV + 8);
    }

    // ---------------- Per-warp write-back ----------------
    __syncthreads();    // all warps done with stash region before sRed overwrite
    {
        float2 f;
        f = upk2(P0); sRed[warp][0][lane] = f.x; sRed[warp][0][lane+32] = f.y;
        f = upk2(P1); sRed[warp][1][lane] = f.x; sRed[warp][1][lane+32] = f.y;
        f = upk2(P2); sRed[warp][2][lane] = f.x; sRed[warp][2][lane+32] = f.y;
        f = upk2(P3); sRed[warp][3][lane] = f.x; sRed[warp][3][lane+32] = f.y;
    }
    sOwn += __shfl_xor_sync(0xffffffffu, sOwn, 1);
    sOwn += __shfl_xor_sync(0xffffffffu, sOwn, 2);
    sOwn += __shfl_xor_sync(0xffffffffu, sOwn, 4);
    if (s == 0) sWsum[warp][h] = sOwn * 0.5f;   // dedupe the s / s+4 duplication
    __syncthreads();

    // ---------------- Finalize: normalize, @enc_w2, output MLP ----------------
    if (tid < 4) {
        float ss = 0.f;
        #pragma unroll
        for (int w = 0; w < WARPS; w++) ss += sWsum[w][tid];
        sSum[tid] = ss;
    }
    __syncthreads();
    if (tid < 256) {
        const int hh = tid >> 6, j = tid & 63;
        float acc = 0.f;
        #pragma unroll
        for (int w = 0; w < WARPS; w++) acc += sRed[w][hh][j];
        sPooledF[hh*64 + j] = acc / sSum[hh];   // overlays sWexp (dead)
    }
    __syncthreads();
    if (tid < 256) {
        const int hh = tid >> 6, d = tid & 63;
        float acc = enc_b2[d];
        #pragma unroll 8
        for (int k = 0; k < 64; k++)
            acc = fmaf(sPooledF[hh*64 + k], enc_w2[k*64 + d], acc);
        sCtxF[hh*64 + d] = acc;     // head-major, matches reshape(B, H*HID)
    }
    __syncthreads();
    if (tid < 64) {
        float acc = out_b1[tid];
        #pragma unroll 8
        for (int c = 0; c < 256; c++)
            acc = fmaf(sCtxF[c], out_w1[c*64 + tid], acc);
        sOF[tid] = fmaxf(acc, 0.f);
    }
    __syncthreads();
    if (tid < 32) {
        float v = sOF[tid]*out_w2[tid] + sOF[tid+32]*out_w2[tid+32];
        #pragma unroll
        for (int o = 16; o > 0; o >>= 1)
            v += __shfl_xor_sync(0xffffffffu, v, o);
        if (tid == 0) out[b] = v + out_b2[0];
    }
}

extern "C" void kernel_launch(void* const* d_in, const int* in_sizes, int n_in,
                              void* d_out, int out_size)
{
    const float* radar_xy  = (const float*)d_in[0];
    const float* radar_dir = (const float*)d_in[1];
    const float* pts       = (const float*)d_in[2];
    const float* enc_w1    = (const float*)d_in[3];
    const float* enc_b1    = (const float*)d_in[4];
    const float* enc_w2    = (const float*)d_in[5];
    const float* enc_b2    = (const float*)d_in[6];
    const float* sc_w1     = (const float*)d_in[7];
    const float* sc_b1     = (const float*)d_in[8];
    const float* sc_w2     = (const float*)d_in[9];
    const float* sc_b2     = (const float*)d_in[10];
    const float* out_w1    = (const float*)d_in[11];
    const float* out_b1    = (const float*)d_in[12];
    const float* out_w2    = (const float*)d_in[13];
    const float* out_b2    = (const float*)d_in[14];
    float* out = (float*)d_out;

    mha_fused_kernel<<<Bq, THREADS>>>(
        radar_xy, radar_dir, pts,
        enc_w1, enc_b1, enc_w2, enc_b2,
        sc_w1, sc_b1, sc_w2, sc_b2,
        out_w1, out_b1, out_w2, out_b2,
        out);
}

// round 16
// speedup vs baseline: 1.1204x; 1.1204x over previous
#include <cuda_runtime.h>

// Problem constants (fixed by setup_inputs)
#define Bq      128
#define Nq      8192
#define THREADS 1024
#define WARPS   32
#define PPW     256        // points per warp
#define CHUNKS  4
#define CITER   16         // 4-point iterations per chunk (64 pts per chunk)

#define LOG2E 1.4426950408889634f

typedef unsigned long long ull;

// ---- Blackwell packed fp32x2 helpers (FFMA2 only reachable via PTX) ----
static __device__ __forceinline__ ull pk2(float lo, float hi) {
    ull r; asm("mov.b64 %0, {%1, %2};" : "=l"(r) : "f"(lo), "f"(hi)); return r;
}
static __device__ __forceinline__ ull ffma2(ull a, ull b, ull c) {
    ull d; asm("fma.rn.f32x2 %0, %1, %2, %3;" : "=l"(d) : "l"(a), "l"(b), "l"(c)); return d;
}
static __device__ __forceinline__ float2 upk2(ull v) {
    float2 f; asm("mov.b64 {%0, %1}, %2;" : "=f"(f.x), "=f"(f.y) : "l"(v)); return f;
}
static __device__ __forceinline__ ull relu2(ull v) {
    float2 f = upk2(v);
    return pk2(fmaxf(f.x, 0.f), fmaxf(f.y, 0.f));
}

__global__ __launch_bounds__(THREADS, 1)
void mha_fused_kernel(const float* __restrict__ radar_xy,
                      const float* __restrict__ radar_dir,
                      const float* __restrict__ pts,
                      const float* __restrict__ enc_w1,
                      const float* __restrict__ enc_b1,
                      const float* __restrict__ enc_w2,
                      const float* __restrict__ enc_b2,
                      const float* __restrict__ sc_w1,
                      const float* __restrict__ sc_b1,
                      const float* __restrict__ sc_w2,
                      const float* __restrict__ sc_b2,
                      const float* __restrict__ out_w1,
                      const float* __restrict__ out_b1,
                      const float* __restrict__ out_w2,
                      const float* __restrict__ out_b2,
                      float* __restrict__ out)
{
    __shared__ ulonglong2 sAB[4][32];    // (a-pair px, b-pair py) — reloaded to regs per chunk
    __shared__ ulonglong2 sCV[4][32];    // (c-pair bias, v-pair w2) — 4 LDS.128 per stage-A
    __shared__ ull        sE1p[32], sE2p[32], sBEp[32];  // encoder packed (j, j+32)
    __shared__ float      sWsum[WARPS][4];
    __shared__ float      sSum[4];
    __shared__ float      sPooled[4][64];
    __shared__ float      sCtx[256];
    __shared__ float      sO[64];
    // Dual-use block (256 floats per warp):
    //   during loop:  weight strip  [warp][iter(16)][pt*4+h (16)]
    //   after loop:   sRed          [warp][head(4)][feat(64)]
    __shared__ __align__(16) float sBig[WARPS * 256];

    const int b    = blockIdx.x;
    const int tid  = threadIdx.x;
    const int warp = tid >> 5;
    const int lane = tid & 31;

    const float r0 = radar_xy[b*2+0], r1 = radar_xy[b*2+1];
    const float r2 = radar_dir[b*2+0], r3 = radar_dir[b*2+1];

    // ---------------- Staging (identical to R9) ----------------
    if (tid < 128) {
        const int k = tid >> 5, hs = tid & 31;
        const int hh = hs >> 3, j = (hs & 7) * 8 + k * 2;
        const float* w = sc_w1 + (size_t)hh * 384;
        const float c0 = sc_b1[hh*64+j]   + r0*w[j]   + r1*w[64+j]   + r2*w[128+j]   + r3*w[192+j];
        const float c1 = sc_b1[hh*64+j+1] + r0*w[j+1] + r1*w[64+j+1] + r2*w[128+j+1] + r3*w[192+j+1];
        ulonglong2 cv;
        cv.x = pk2(c0, c1);
        cv.y = pk2(sc_w2[hh*64+j], sc_w2[hh*64+j+1]);
        sCV[k][hs] = cv;
    } else if (tid < 224) {
        const int idx = tid - 128, arr = idx >> 5, l = idx & 31;
        if (arr == 0)      sE1p[l] = pk2(enc_w1[256+l], enc_w1[256+l+32]);
        else if (arr == 1) sE2p[l] = pk2(enc_w1[320+l], enc_w1[320+l+32]);
        else {
            const float b0 = enc_b1[l]    + r0*enc_w1[l]     + r1*enc_w1[64+l]
                                          + r2*enc_w1[128+l]  + r3*enc_w1[192+l];
            const float b1 = enc_b1[l+32] + r0*enc_w1[l+32]  + r1*enc_w1[64+l+32]
                                          + r2*enc_w1[128+l+32] + r3*enc_w1[192+l+32];
            sBEp[l] = pk2(b0, b1);
        }
    } else if (tid >= 256 && tid < 384) {
        const int idx = tid - 256;
        const int k = idx >> 5, hs = idx & 31;
        const int hh = hs >> 3, j = (hs & 7) * 8 + k * 2;
        const float* w = sc_w1 + (size_t)hh * 384;
        ulonglong2 ab;
        ab.x = pk2(w[256+j], w[256+j+1]);   // row 4: px coeffs
        ab.y = pk2(w[320+j], w[320+j+1]);   // row 5: py coeffs
        sAB[k][hs] = ab;
    }
    __syncthreads();

    // ---------------- Per-lane constants ----------------
    const int h = lane >> 3, s = lane & 7;
    const float b2l = sc_b2[h] * LOG2E;
    // After the butterfly, lane s holds point p(s) = (s&1)*2 + ((s>>1)&1)
    const int pOwnH = (((s & 1) << 1) + ((s >> 1) & 1)) * 4 + h;
    const bool sel1 = (s & 1) != 0, sel2 = (s & 2) != 0;

    const ull e1p = sE1p[lane], e2p = sE2p[lane], bep = sBEp[lane];

    float p00=0.f,p01=0.f,p10=0.f,p11=0.f,p20=0.f,p21=0.f,p30=0.f,p31=0.f;
    float sOwn = 0.f;

    const float4* P4 = reinterpret_cast<const float4*>(pts)
                     + ((size_t)b * (Nq/2) + (size_t)warp * (PPW/2));
    float* wbase = sBig + warp * 256;

    // ---------------- Main loop: 4 chunks of (16×A, sync, 16×B, sync) ----------------
    #pragma unroll 1
    for (int c = 0; c < CHUNKS; c++) {
        // ======== A-run: 16 independent logit/exp iterations ========
        {
            ull aK[4], bK[4];   // live only in the A-run (reloaded per chunk)
            #pragma unroll
            for (int k = 0; k < 4; k++) {
                ulonglong2 t = sAB[k][lane]; aK[k] = t.x; bK[k] = t.y;
            }
            #pragma unroll 2
            for (int i = 0; i < CITER; i++) {
                const int idx = c * CITER + i;
                const float4 qa = __ldg(P4 + 2*idx);
                const float4 qb = __ldg(P4 + 2*idx + 1);
                const ull px0 = pk2(qa.x,qa.x), py0 = pk2(qa.y,qa.y);
                const ull px1 = pk2(qa.z,qa.z), py1 = pk2(qa.w,qa.w);
                const ull px2 = pk2(qb.x,qb.x), py2 = pk2(qb.y,qb.y);
                const ull px3 = pk2(qb.z,qb.z), py3 = pk2(qb.w,qb.w);

                ull ac0, ac1, ac2, ac3;
                {
                    ulonglong2 cv = sCV[0][lane];
                    ac0 = ffma2(relu2(ffma2(py0,bK[0], ffma2(px0,aK[0], cv.x))), cv.y, 0ull);
                    ac1 = ffma2(relu2(ffma2(py1,bK[0], ffma2(px1,aK[0], cv.x))), cv.y, 0ull);
                    ac2 = ffma2(relu2(ffma2(py2,bK[0], ffma2(px2,aK[0], cv.x))), cv.y, 0ull);
                    ac3 = ffma2(relu2(ffma2(py3,bK[0], ffma2(px3,aK[0], cv.x))), cv.y, 0ull);
                    cv = sCV[1][lane];
                    ac0 = ffma2(relu2(ffma2(py0,bK[1], ffma2(px0,aK[1], cv.x))), cv.y, ac0);
                    ac1 = ffma2(relu2(ffma2(py1,bK[1], ffma2(px1,aK[1], cv.x))), cv.y, ac1);
                    ac2 = ffma2(relu2(ffma2(py2,bK[1], ffma2(px2,aK[1], cv.x))), cv.y, ac2);
                    ac3 = ffma2(relu2(ffma2(py3,bK[1], ffma2(px3,aK[1], cv.x))), cv.y, ac3);
                    cv = sCV[2][lane];
                    ac0 = ffma2(relu2(ffma2(py0,bK[2], ffma2(px0,aK[2], cv.x))), cv.y, ac0);
                    ac1 = ffma2(relu2(ffma2(py1,bK[2], ffma2(px1,aK[2], cv.x))), cv.y, ac1);
                    ac2 = ffma2(relu2(ffma2(py2,bK[2], ffma2(px2,aK[2], cv.x))), cv.y, ac2);
                    ac3 = ffma2(relu2(ffma2(py3,bK[2], ffma2(px3,aK[2], cv.x))), cv.y, ac3);
                    cv = sCV[3][lane];
                    ac0 = ffma2(relu2(ffma2(py0,bK[3], ffma2(px0,aK[3], cv.x))), cv.y, ac0);
                    ac1 = ffma2(relu2(ffma2(py1,bK[3], ffma2(px1,aK[3], cv.x))), cv.y, ac1);
                    ac2 = ffma2(relu2(ffma2(py2,bK[3], ffma2(px2,aK[3], cv.x))), cv.y, ac2);
                    ac3 = ffma2(relu2(ffma2(py3,bK[3], ffma2(px3,aK[3], cv.x))), cv.y, ac3);
                }
                float2 t;
                t = upk2(ac0); float a0 = t.x + t.y;
                t = upk2(ac1); float a1 = t.x + t.y;
                t = upk2(ac2); float a2 = t.x + t.y;
                t = upk2(ac3); float a3 = t.x + t.y;

                // batched butterfly over 8 lanes: 4 shfl / 4 points
                const float r0s = __shfl_xor_sync(0xffffffffu, sel1 ? a0 : a2, 1);
                const float r1s = __shfl_xor_sync(0xffffffffu, sel1 ? a1 : a3, 1);
                a0 = (sel1 ? a2 : a0) + r0s;
                a1 = (sel1 ? a3 : a1) + r1s;
                const float r2s = __shfl_xor_sync(0xffffffffu, sel2 ? a0 : a1, 2);
                float v = (sel2 ? a1 : a0) + r2s;
                v += __shfl_xor_sync(0xffffffffu, v, 4);

                const float w = exp2f(fmaf(v, LOG2E, b2l));
                sOwn += w;                      // each (pt,h) counted twice per 8-group (x0.5 later)
                if (s < 4) wbase[i*16 + pOwnH] = w;   // 16 consecutive floats: conflict-free
            }
        }
        __syncwarp();    // weight strip visible to whole warp

        // ======== B-run: 16 independent encoder/pooling iterations ========
        #pragma unroll 2
        for (int i = 0; i < CITER; i++) {
            const int idx = c * CITER + i;
            const float4 qa = __ldg(P4 + 2*idx);        // L1-hot (A-run just read it)
            const float4 qb = __ldg(P4 + 2*idx + 1);
            const float4* wv4 = reinterpret_cast<const float4*>(wbase + i*16);
            const float4 wv0 = wv4[0];   // point 0: (h0,h1,h2,h3) — broadcast LDS.128
            const float4 wv1 = wv4[1];
            const float4 wv2 = wv4[2];
            const float4 wv3 = wv4[3];

            float2 h2;
            h2 = upk2(relu2(ffma2(pk2(qa.y,qa.y), e2p, ffma2(pk2(qa.x,qa.x), e1p, bep))));
            p00 = fmaf(wv0.x, h2.x, p00); p01 = fmaf(wv0.x, h2.y, p01);
            p10 = fmaf(wv0.y, h2.x, p10); p11 = fmaf(wv0.y, h2.y, p11);
            p20 = fmaf(wv0.z, h2.x, p20); p21 = fmaf(wv0.z, h2.y, p21);
            p30 = fmaf(wv0.w, h2.x, p30); p31 = fmaf(wv0.w, h2.y, p31);
            h2 = upk2(relu2(ffma2(pk2(qa.w,qa.w), e2p, ffma2(pk2(qa.z,qa.z), e1p, bep))));
            p00 = fmaf(wv1.x, h2.x, p00); p01 = fmaf(wv1.x, h2.y, p01);
            p10 = fmaf(wv1.y, h2.x, p10); p11 = fmaf(wv1.y, h2.y, p11);
            p20 = fmaf(wv1.z, h2.x, p20); p21 = fmaf(wv1.z, h2.y, p21);
            p30 = fmaf(wv1.w, h2.x, p30); p31 = fmaf(wv1.w, h2.y, p31);
            h2 = upk2(relu2(ffma2(pk2(qb.y,qb.y), e2p, ffma2(pk2(qb.x,qb.x), e1p, bep))));
            p00 = fmaf(wv2.x, h2.x, p00); p01 = fmaf(wv2.x, h2.y, p01);
            p10 = fmaf(wv2.y, h2.x, p10); p11 = fmaf(wv2.y, h2.y, p11);
            p20 = fmaf(wv2.z, h2.x, p20); p21 = fmaf(wv2.z, h2.y, p21);
            p30 = fmaf(wv2.w, h2.x, p30); p31 = fmaf(wv2.w, h2.y, p31);
            h2 = upk2(relu2(ffma2(pk2(qb.w,qb.w), e2p, ffma2(pk2(qb.z,qb.z), e1p, bep))));
            p00 = fmaf(wv3.x, h2.x, p00); p01 = fmaf(wv3.x, h2.y, p01);
            p10 = fmaf(wv3.y, h2.x, p10); p11 = fmaf(wv3.y, h2.y, p11);
            p20 = fmaf(wv3.z, h2.x, p20); p21 = fmaf(wv3.z, h2.y, p21);
            p30 = fmaf(wv3.w, h2.x, p30); p31 = fmaf(wv3.w, h2.y, p31);
        }
        __syncwarp();    // strip reusable by next chunk's A-run
    }

    // ---------------- Per-warp write-back (own sBig block — no block sync needed) ----------------
    {
        float* sRedW = sBig + warp * 256;   // [head][feat]
        sRedW[0*64 + lane] = p00; sRedW[0*64 + lane+32] = p01;
        sRedW[1*64 + lane] = p10; sRedW[1*64 + lane+32] = p11;
        sRedW[2*64 + lane] = p20; sRedW[2*64 + lane+32] = p21;
        sRedW[3*64 + lane] = p30; sRedW[3*64 + lane+32] = p31;
    }
    sOwn += __shfl_xor_sync(0xffffffffu, sOwn, 1);
    sOwn += __shfl_xor_sync(0xffffffffu, sOwn, 2);
    sOwn += __shfl_xor_sync(0xffffffffu, sOwn, 4);
    if (s == 0) sWsum[warp][h] = sOwn * 0.5f;   // dedupe the s / s+4 duplication
    __syncthreads();

    // ---------------- Finalize: normalize, @enc_w2, output MLP ----------------
    if (tid < 4) {
        float ss = 0.f;
        #pragma unroll
        for (int w = 0; w < WARPS; w++) ss += sWsum[w][tid];
        sSum[tid] = ss;
    }
    __syncthreads();
    if (tid < 256) {
        const int hh = tid >> 6, j = tid & 63;
        float acc = 0.f;
        #pragma unroll
        for (int w = 0; w < WARPS; w++) acc += sBig[w*256 + hh*64 + j];
        sPooled[hh][j] = acc / sSum[hh];
    }
    __syncthreads();
    if (tid < 256) {
        const int hh = tid >> 6, d = tid & 63;
        float acc = enc_b2[d];
        #pragma unroll 8
        for (int k = 0; k < 64; k++)
            acc = fmaf(sPooled[hh][k], enc_w2[k*64 + d], acc);
        sCtx[hh*64 + d] = acc;     // head-major, matches reshape(B, H*HID)
    }
    __syncthreads();
    if (tid < 64) {
        float acc = out_b1[tid];
        #pragma unroll 8
        for (int c = 0; c < 256; c++)
            acc = fmaf(sCtx[c], out_w1[c*64 + tid], acc);
        sO[tid] = fmaxf(acc, 0.f);
    }
    __syncthreads();
    if (tid < 32) {
        float v = sO[tid]*out_w2[tid] + sO[tid+32]*out_w2[tid+32];
        #pragma unroll
        for (int o = 16; o > 0; o >>= 1)
            v += __shfl_xor_sync(0xffffffffu, v, o);
        if (tid == 0) out[b] = v + out_b2[0];
    }
}

extern "C" void kernel_launch(void* const* d_in, const int* in_sizes, int n_in,
                              void* d_out, int out_size)
{
    const float* radar_xy  = (const float*)d_in[0];
    const float* radar_dir = (const float*)d_in[1];
    const float* pts       = (const float*)d_in[2];
    const float* enc_w1    = (const float*)d_in[3];
    const float* enc_b1    = (const float*)d_in[4];
    const float* enc_w2    = (const float*)d_in[5];
    const float* enc_b2    = (const float*)d_in[6];
    const float* sc_w1     = (const float*)d_in[7];
    const float* sc_b1     = (const float*)d_in[8];
    const float* sc_w2     = (const float*)d_in[9];
    const float* sc_b2     = (const float*)d_in[10];
    const float* out_w1    = (const float*)d_in[11];
    const float* out_b1    = (const float*)d_in[12];
    const float* out_w2    = (const float*)d_in[13];
    const float* out_b2    = (const float*)d_in[14];
    float* out = (float*)d_out;

    mha_fused_kernel<<<Bq, THREADS>>>(
        radar_xy, radar_dir, pts,
        enc_w1, enc_b1, enc_w2, enc_b2,
        sc_w1, sc_b1, sc_w2, sc_b2,
        out_w1, out_b1, out_w2, out_b2,
        out);
}